// round 7
// baseline (speedup 1.0000x reference)
#include <cuda_runtime.h>
#include <cstdint>

#define NX 13
#define NN 169                // 13*13
#define BOLTZ 5.67e-08f
#define WPB 8                 // warps per block
#define BT 256                // block threads
#define NBLK 3                // target blocks/SM
#define GRID 444              // 148 SMs * 3
#define GPW 2                 // batches per group
#define GRP_BYTES (GPW * NN * 4)   // 1352
#define WIN_BYTES 1360             // aligned-down window: 1352 + up to 8 slack
#define NWIN 85                    // float4 per array per window (1360/16)
#define TE_OFF 344                 // float offset of Tenv region inside a stage
#define STAGEF 688                 // stage floats: [T 340|pad 4|Tenv 340|pad 4]
#define NSTAGE 3
#define WCHUNK (NSTAGE * STAGEF)   // 2064 floats per warp
#define FRONT_GUARD 16
#define REAR_GUARD 64
#define SMEM_FLOATS (FRONT_GUARD + WPB * WCHUNK + REAR_GUARD)  // 16592
#define SMEM_BYTES (SMEM_FLOATS * 4)                           // 66368

static __device__ double g_partials[GRID];
static __device__ unsigned int g_count = 0;   // wraps to 0 every run -> replay-safe

__device__ __forceinline__ void cp16(unsigned dst, const void* src) {
    asm volatile("cp.async.cg.shared.global [%0], [%1], 16;" :: "r"(dst), "l"(src));
}
__device__ __forceinline__ void cp16z(unsigned dst, const void* src, int srcBytes) {
    asm volatile("cp.async.cg.shared.global [%0], [%1], 16, %2;"
                 :: "r"(dst), "l"(src), "r"(srcBytes));
}
__device__ __forceinline__ void cp_commit() {
    asm volatile("cp.async.commit_group;" ::: "memory");
}
__device__ __forceinline__ void cp_wait1() {
    asm volatile("cp.async.wait_group 1;" ::: "memory");
}

// Prefetch group g (16B-aligned window) into stageBuf.
__device__ __forceinline__ void prefetch_group(
    const char* __restrict__ gT, const char* __restrict__ gE,
    size_t totalBytes, int g, float* stageBuf, int lane)
{
    size_t srcByte  = (size_t)g * GRP_BYTES;
    size_t aligned  = srcByte & ~(size_t)15;
    unsigned dT = (unsigned)__cvta_generic_to_shared(stageBuf);
    unsigned dE = (unsigned)__cvta_generic_to_shared(stageBuf + TE_OFF);
    if (aligned + WIN_BYTES <= totalBytes) {
        #pragma unroll
        for (int m = 0; m < 3; m++) {
            int idx = lane + 32 * m;
            if (idx < NWIN) {
                size_t o = aligned + (size_t)idx * 16;
                cp16(dT + idx * 16, gT + o);
                cp16(dE + idx * 16, gE + o);
            }
        }
    } else {
        long base = (long)aligned;
        #pragma unroll
        for (int m = 0; m < 3; m++) {
            int idx = lane + 32 * m;
            if (idx < NWIN) {
                long o  = base + (long)idx * 16;
                long rb = (long)totalBytes - o;
                int sb  = (int)min((long)16, max((long)0, rb));
                long so = (sb > 0) ? o : 0;
                cp16z(dT + idx * 16, gT + so, sb);
                cp16z(dE + idx * 16, gE + so, sb);
            }
        }
    }
}

__device__ __forceinline__ float load_q(const float* __restrict__ heaters,
                                        const float* __restrict__ interf,
                                        int g, int B, int lane)
{
    // lanes 0..7: heaters of batches 2g,2g+1; lanes 16..23: interfaces
    int j = g * 8 + (lane & 7);
    float q = 0.f;
    if ((lane & 8) == 0 && j < B * 4)
        q = (lane < 16) ? __ldg(heaters + j) : __ldg(interf + j);
    return q;
}

__global__ __launch_bounds__(BT, NBLK)
void excess_kernel(const float* __restrict__ T,        // [B,169]
                   const float* __restrict__ heaters,  // [B,4]
                   const float* __restrict__ interf,   // [B,4]
                   const float* __restrict__ Tenv,     // [B,169]
                   const float* __restrict__ K,        // [169,169]
                   const float* __restrict__ E,        // [169]
                   float* __restrict__ out,
                   int B, double invCount)
{
    extern __shared__ float smem[];
    __shared__ double blockSums[WPB];
    __shared__ double smr[BT];
    __shared__ bool   isLast;

    const int tid  = threadIdx.x;
    const int lane = tid & 31;
    const int wid  = tid >> 5;

    // Zero all dynamic smem once: guards + buffers start finite.
    for (int i = tid; i < SMEM_FLOATS; i += BT) smem[i] = 0.f;
    __syncthreads();

    float* warpBuf = smem + FRONT_GUARD + wid * WCHUNK;

    // Per-lane per-k constants from K/E (L2-resident). Band read reproduces
    // dense K@T exactly: all nonzeros lie on {diag,+-1,+-NX}; unwritten
    // in-range band entries are 0.0f in the dense matrix.
    float c0[6], cL[6], cR[6], cU[6], cD[6], sE[6], qm[6];
    int qo[6];
    #pragma unroll
    for (int k = 0; k < 6; k++) {
        int n = lane + 32 * k;
        bool in = (n < NN);
        c0[k] = in               ? __ldg(K + n * NN + n)      : 0.f;
        cL[k] = (in && n >= 1)   ? __ldg(K + n * NN + n - 1)  : 0.f;
        cR[k] = (in && n+1 < NN) ? __ldg(K + n * NN + n + 1)  : 0.f;
        cU[k] = (in && n >= NX)  ? __ldg(K + n * NN + n - NX) : 0.f;
        cD[k] = (in && n+NX < NN)? __ldg(K + n * NN + n + NX) : 0.f;
        sE[k] = in               ? BOLTZ * __ldg(E + n)       : 0.f;
        int o = 0; float m = 0.f;
        if      (n ==  81) { o = 0;  m = 1.f; }   // heaters[:,0]
        else if (n ==  45) { o = 1;  m = 1.f; }   // heaters[:,1]
        else if (n == 120) { o = 2;  m = 1.f; }   // heaters[:,2]
        else if (n == 126) { o = 3;  m = 1.f; }   // heaters[:,3]
        else if (n ==   0) { o = 16; m = 1.f; }   // interfaces[:,0]
        else if (n ==  12) { o = 17; m = 1.f; }   // interfaces[:,1]
        else if (n == 168) { o = 18; m = 1.f; }   // interfaces[:,2]
        else if (n == 156) { o = 19; m = 1.f; }   // interfaces[:,3]
        qo[k] = o; qm[k] = m;
    }

    const char* gT = (const char*)T;
    const char* gE = (const char*)Tenv;
    const size_t totalBytes = (size_t)B * NN * 4;
    const int nG = (B + GPW - 1) / GPW;
    const int ws = GRID * WPB;               // warp stride in groups

    int g = blockIdx.x * WPB + wid;
    float qA = 0.f, qB = 0.f, qC;
    float acc = 0.f;
    int s = 0;

    // Prologue: fill 2 pipeline stages
    if (g < nG) { prefetch_group(gT, gE, totalBytes, g, warpBuf, lane);
                  qA = load_q(heaters, interf, g, B, lane); }
    cp_commit();
    if (g + ws < nG) { prefetch_group(gT, gE, totalBytes, g + ws, warpBuf + STAGEF, lane);
                       qB = load_q(heaters, interf, g + ws, B, lane); }
    cp_commit();

    for (; g < nG; g += ws) {
        cp_wait1();          // oldest pending (this iteration's group) has landed
        __syncwarp();

        const int g2 = g + 2 * ws;
        int s2 = s + 2; if (s2 >= NSTAGE) s2 -= NSTAGE;
        if (g2 < nG) { prefetch_group(gT, gE, totalBytes, g2, warpBuf + s2 * STAGEF, lane);
                       qC = load_q(heaters, interf, g2, B, lane); }
        else qC = 0.f;
        cp_commit();

        // compute group g from stage s; uniform start offset 2*(g&1) floats
        const float* base = warpBuf + s * STAGEF + 2 * (g & 1);
        #pragma unroll
        for (int bb = 0; bb < GPW; bb++) {
            const float* p = base + bb * NN + lane;
            #pragma unroll
            for (int k = 0; k < 6; k++) {
                const int o = 32 * k;
                float t  = p[o];
                float tl = p[o - 1];
                float tr = p[o + 1];
                float tu = p[o - NX];
                float td = p[o + NX];
                float te = p[o + TE_OFF];
                float cond = c0[k] * t;
                cond = fmaf(cL[k], tl, cond);
                cond = fmaf(cR[k], tr, cond);
                cond = fmaf(cU[k], tu, cond);
                cond = fmaf(cD[k], td, cond);
                float qk = qm[k] * __shfl_sync(0xffffffffu, qA, qo[k] + bb * 4);
                float t2 = t * t, te2 = te * te;
                float d  = fmaf(t2, t2, -(te2 * te2));
                float ex = fmaf(sE[k], d, cond - qk);
                acc += fabsf(ex);
            }
        }
        s++; if (s >= NSTAGE) s = 0;
        qA = qB; qB = qC;
    }

    // warp reduce (fp32: each lane sums only ~450 O(1) terms)
    #pragma unroll
    for (int off = 16; off; off >>= 1)
        acc += __shfl_down_sync(0xffffffffu, acc, off);
    if (lane == 0) blockSums[wid] = (double)acc;
    __syncthreads();

    if (tid == 0) {
        double sum = 0.0;
        #pragma unroll
        for (int w = 0; w < WPB; w++) sum += blockSums[w];
        g_partials[blockIdx.x] = sum;
        __threadfence();
        unsigned int old = atomicInc(&g_count, GRID - 1);  // wraps -> replay-safe
        isLast = (old == GRID - 1);
    }
    __syncthreads();

    if (isLast) {
        double sum = 0.0;
        for (int i = tid; i < GRID; i += BT) sum += g_partials[i];
        smr[tid] = sum;
        __syncthreads();
        for (int off = BT / 2; off; off >>= 1) {
            if (tid < off) smr[tid] += smr[tid + off];
            __syncthreads();
        }
        if (tid == 0) out[0] = (float)(smr[0] * invCount);
    }
}

extern "C" void kernel_launch(void* const* d_in, const int* in_sizes, int n_in,
                              void* d_out, int out_size)
{
    const float* T       = (const float*)d_in[0];  // outputs [B,13,13]
    const float* heaters = (const float*)d_in[1];  // [B,4]
    const float* interf  = (const float*)d_in[2];  // [B,4]
    const float* Tenv    = (const float*)d_in[3];  // [B,169]
    const float* K       = (const float*)d_in[4];  // [169,169]
    const float* E       = (const float*)d_in[5];  // [169]

    const int B = in_sizes[0] / NN;
    const double invCount = 1.0 / ((double)B * (double)NN);

    cudaFuncSetAttribute(excess_kernel,
                         cudaFuncAttributeMaxDynamicSharedMemorySize, SMEM_BYTES);

    excess_kernel<<<GRID, BT, SMEM_BYTES>>>(T, heaters, interf, Tenv, K, E,
                                            (float*)d_out, B, invCount);
}